// round 9
// baseline (speedup 1.0000x reference)
#include <cuda_runtime.h>
#include <math.h>

#define NQ 512
#define NK 1024
#define DIM 256
#define HEADS 8
#define HD 32
#define RPE 512
#define SCALE 0.17677669529663687f
#define FULLMASK 0xffffffffu

// ---------------- packed fp32x2 helpers ----------------------------------
__device__ __forceinline__ unsigned long long pk2(float lo, float hi) {
  unsigned long long r;
  asm("mov.b64 %0, {%1, %2};" : "=l"(r) : "f"(lo), "f"(hi));
  return r;
}
__device__ __forceinline__ void upk2(float& lo, float& hi, unsigned long long v) {
  asm("mov.b64 {%0, %1}, %2;" : "=f"(lo), "=f"(hi) : "l"(v));
}
__device__ __forceinline__ void fma2(unsigned long long& d, unsigned long long a,
                                     unsigned long long b) {
  asm("fma.rn.f32x2 %0, %1, %2, %0;" : "+l"(d) : "l"(a), "l"(b));
}

// ---------------- scratch (device globals; no allocation) ----------------
__device__ float g_q[NQ * DIM];
__device__ float g_kT[DIM * NK];  // K TRANSPOSED: [d][key]
__device__ float g_v[NK * DIM];
__device__ float g_tsort[RPE];
__device__ float g_F[HEADS * (RPE + 1)];
__device__ float g_G[HEADS * (RPE + 1)];
__device__ unsigned short g_sidx[NQ * NK];

// ---------------- prep: fused QKV GEMMs (32x128 tiles) + CPB precompute --
// blocks 0..159: gemm tiles (Q:0-31, K:32-95, V:96-159), block 160: cpb
__global__ void __launch_bounds__(512) prep(
    const float* __restrict__ query, const float* __restrict__ kin,
    const float* __restrict__ vin,
    const float* __restrict__ Wq, const float* __restrict__ bq,
    const float* __restrict__ Wk, const float* __restrict__ bk,
    const float* __restrict__ Wv, const float* __restrict__ bv,
    const float* __restrict__ W1v, const float* __restrict__ b1v,
    const float* __restrict__ W2v) {
  int t = threadIdx.x;
  if (blockIdx.x < 160) {
    // ------------------ GEMM part: 32 rows x 128 cols, 2x4/thread -------
    __shared__ float As[16][36];
    __shared__ float Bs[16][128];
    int idx = blockIdx.x;
    int sel, tloc;
    if (idx < 32) { sel = 0; tloc = idx; }
    else if (idx < 96) { sel = 1; tloc = idx - 32; }
    else { sel = 2; tloc = idx - 96; }
    const float* A = (sel == 0) ? query : (sel == 1) ? kin : vin;
    const float* W = (sel == 0) ? Wq : (sel == 1) ? Wk : Wv;
    const float* bias = (sel == 0) ? bq : (sel == 1) ? bk : bv;
    float* C = (sel == 0) ? g_q : (sel == 1) ? g_kT : g_v;

    int bm = (tloc >> 1) * 32, bn = (tloc & 1) * 128;
    int tx = t & 31, ty = t >> 5;  // tx: 32 col-groups of 4, ty: 16 row-groups of 2
    float acc[2][4] = {};

    for (int k0 = 0; k0 < 256; k0 += 16) {
      if (t < 128) {  // A tile: 32 rows x 16 k, transposed into As
        int r = t >> 2, c4 = t & 3;
        float4 av = *(const float4*)&A[(bm + r) * 256 + k0 + c4 * 4];
        As[c4 * 4 + 0][r] = av.x;
        As[c4 * 4 + 1][r] = av.y;
        As[c4 * 4 + 2][r] = av.z;
        As[c4 * 4 + 3][r] = av.w;
      }
      {  // W tile: 16 k x 128 cols, one float4 per thread
        int r = t >> 5, c4 = t & 31;
        *(float4*)&Bs[r][c4 * 4] = *(const float4*)&W[(k0 + r) * 256 + bn + c4 * 4];
      }
      __syncthreads();
#pragma unroll
      for (int k = 0; k < 16; k++) {
        float a0 = As[k][ty * 2 + 0];
        float a1 = As[k][ty * 2 + 1];
        float4 b4 = *(const float4*)&Bs[k][tx * 4];
        acc[0][0] = fmaf(a0, b4.x, acc[0][0]);
        acc[0][1] = fmaf(a0, b4.y, acc[0][1]);
        acc[0][2] = fmaf(a0, b4.z, acc[0][2]);
        acc[0][3] = fmaf(a0, b4.w, acc[0][3]);
        acc[1][0] = fmaf(a1, b4.x, acc[1][0]);
        acc[1][1] = fmaf(a1, b4.y, acc[1][1]);
        acc[1][2] = fmaf(a1, b4.z, acc[1][2]);
        acc[1][3] = fmaf(a1, b4.w, acc[1][3]);
      }
      __syncthreads();
    }
    if (sel == 1) {  // transposed: g_kT[col][row]
#pragma unroll
      for (int i = 0; i < 2; i++) {
        int row = bm + ty * 2 + i;
#pragma unroll
        for (int j = 0; j < 4; j++) {
          int col = bn + tx * 4 + j;
          C[col * NK + row] = acc[i][j] + bias[col];
        }
      }
    } else {
#pragma unroll
      for (int i = 0; i < 2; i++) {
        int row = bm + ty * 2 + i;
#pragma unroll
        for (int j = 0; j < 4; j++) {
          int col = bn + tx * 4 + j;
          C[row * 256 + col] = acc[i][j] + bias[col];
        }
      }
    }
    return;
  }

  // ------------------ CPB precompute part (block 160, 512 threads) ------
  __shared__ float skey[RPE];
  __shared__ int sord[RPE];
  __shared__ float swtA[16][8];
  __shared__ float swtB[16][8];
  __shared__ float sF0[8], sG0[8];
  __shared__ float sTotW[8], sTotB[8];
  int lane = t & 31, warp = t >> 5;

  float w1 = W1v[t], bb = b1v[t];
  skey[t] = (w1 != 0.f) ? (-bb / w1) : INFINITY;
  sord[t] = t;
  __syncthreads();

  for (int size = 2; size <= RPE; size <<= 1) {
    for (int stride = size >> 1; stride > 0; stride >>= 1) {
      int p = t ^ stride;
      if (p > t) {
        bool asc = ((t & size) == 0);
        float k1 = skey[t], k2 = skey[p];
        if ((k1 > k2) == asc) {
          skey[t] = k2;
          skey[p] = k1;
          int tmp = sord[t];
          sord[t] = sord[p];
          sord[p] = tmp;
        }
      }
      __syncthreads();
    }
  }
  g_tsort[t] = skey[t];
  int r = sord[t];
  float w1r = W1v[r], b1r = b1v[r];
  bool isPos = (w1r > 0.f), isNeg = (w1r < 0.f);
  bool isZero = (!isPos && !isNeg);
  float sgn = isPos ? 1.f : (isNeg ? -1.f : 0.f);

  float ocw[8], ocb[8], cw[8], cb[8], f0[8], g0[8];
#pragma unroll
  for (int h = 0; h < 8; h++) {
    float w2 = W2v[r * HEADS + h];
    ocw[h] = sgn * w1r * w2;
    ocb[h] = sgn * b1r * w2;
    cw[h] = ocw[h];
    cb[h] = ocb[h];
    f0[h] = isNeg ? (w1r * w2) : 0.f;
    g0[h] = isNeg ? (b1r * w2) : ((isZero && b1r > 0.f) ? (b1r * w2) : 0.f);
  }

#pragma unroll
  for (int o = 16; o; o >>= 1)
#pragma unroll
    for (int h = 0; h < 8; h++) {
      f0[h] += __shfl_xor_sync(FULLMASK, f0[h], o);
      g0[h] += __shfl_xor_sync(FULLMASK, g0[h], o);
    }
  if (lane == 0)
#pragma unroll
    for (int h = 0; h < 8; h++) {
      swtA[warp][h] = f0[h];
      swtB[warp][h] = g0[h];
    }
  __syncthreads();
  if (t < 8) {
    float sa = 0.f, sb = 0.f;
    for (int ww = 0; ww < 16; ww++) {
      sa += swtA[ww][t];
      sb += swtB[ww][t];
    }
    sF0[t] = sa;
    sG0[t] = sb;
  }
  __syncthreads();

#pragma unroll
  for (int o = 1; o < 32; o <<= 1) {
#pragma unroll
    for (int h = 0; h < 8; h++) {
      float ta = __shfl_up_sync(FULLMASK, cw[h], o);
      float tb = __shfl_up_sync(FULLMASK, cb[h], o);
      if (lane >= o) {
        cw[h] += ta;
        cb[h] += tb;
      }
    }
  }
  if (lane == 31)
#pragma unroll
    for (int h = 0; h < 8; h++) {
      swtA[warp][h] = cw[h];
      swtB[warp][h] = cb[h];
    }
  __syncthreads();

  if (warp == 0) {
    float va[8], vb[8], owa[8], owb[8];
#pragma unroll
    for (int h = 0; h < 8; h++) {
      owa[h] = (lane < 16) ? swtA[lane][h] : 0.f;
      owb[h] = (lane < 16) ? swtB[lane][h] : 0.f;
      va[h] = owa[h];
      vb[h] = owb[h];
    }
#pragma unroll
    for (int o = 1; o < 16; o <<= 1)
#pragma unroll
      for (int h = 0; h < 8; h++) {
        float ta = __shfl_up_sync(FULLMASK, va[h], o);
        float tb = __shfl_up_sync(FULLMASK, vb[h], o);
        if (lane >= o) {
          va[h] += ta;
          vb[h] += tb;
        }
      }
    if (lane < 16) {
#pragma unroll
      for (int h = 0; h < 8; h++) {
        swtA[lane][h] = va[h] - owa[h];
        swtB[lane][h] = vb[h] - owb[h];
        if (lane == 15) {
          sTotW[h] = va[h];
          sTotB[h] = vb[h];
        }
      }
    }
  }
  __syncthreads();

#pragma unroll
  for (int h = 0; h < 8; h++) {
    float excl = (cw[h] - ocw[h]) + swtA[warp][h];
    float exclb = (cb[h] - ocb[h]) + swtB[warp][h];
    g_F[h * (RPE + 1) + t] = sF0[h] + excl;
    g_G[h * (RPE + 1) + t] = sG0[h] + exclb;
  }
  if (t == 0)
#pragma unroll
    for (int h = 0; h < 8; h++) {
      g_F[h * (RPE + 1) + RPE] = sF0[h] + sTotW[h];
      g_G[h * (RPE + 1) + RPE] = sG0[h] + sTotB[h];
    }
}

// ---------------- cpb_index + output init (out = bp broadcast) ----------
__global__ void __launch_bounds__(256) cpb_index(const float* __restrict__ am,
                                                 const float* __restrict__ bp,
                                                 float* __restrict__ outp) {
  __shared__ float st[RPE];
  int t = threadIdx.x;
  for (int i = t; i < RPE; i += 256) st[i] = g_tsort[i];
  // init d_out row blockIdx.x with bias (attention atomically accumulates)
  outp[blockIdx.x * 256 + t] = bp[t];
  __syncthreads();
  int base = (blockIdx.x * 256 + t) * 4;
  float4 a4 = *(const float4*)&am[base];
  float av[4] = {a4.x, a4.y, a4.z, a4.w};
  unsigned short res[4];
#pragma unroll
  for (int u = 0; u < 4; u++) {
    int pos = 0;
#pragma unroll
    for (int sgm = 256; sgm >= 1; sgm >>= 1)
      if (st[pos + sgm - 1] < av[u]) pos += sgm;
    res[u] = (unsigned short)pos;
  }
  *(ushort4*)&g_sidx[base] = make_ushort4(res[0], res[1], res[2], res[3]);
}

// ---------------- fused attention + output projection --------------------
struct AttnSmem {
  float sQ[8][32];  // @0: scaled Q, later reused as x-slice for projection
  union {
    float sP[NK][4];       // 16KB: normalized probs for a 4-qi pass
    float sOut[8][8][32];  // 8KB epilogue
  } u;                     // @1024
  float sRed[8][8];        // @17408 (16B aligned)
  float sF[RPE + 4];
  float sG[RPE + 4];
};  // ~21.4KB -> static shared, 4 blocks/SM

__global__ void __launch_bounds__(256, 4) attention(
    const float* __restrict__ pad, const float* __restrict__ am,
    const float* __restrict__ Wp, float* __restrict__ outp) {
  __shared__ AttnSmem S;
  const int h = blockIdx.y;
  const int q0 = blockIdx.x * 8;
  const int t = threadIdx.x;
  const int lane = t & 31, w = t >> 5;
  const int kbase = 4 * t;

  S.sQ[w][lane] = g_q[(q0 + w) * DIM + h * HD + lane] * SCALE;
  for (int i = t; i <= RPE; i += 256) {
    S.sF[i] = g_F[h * (RPE + 1) + i];
    S.sG[i] = g_G[h * (RPE + 1) + i];
  }
  __syncthreads();

  // ---- QK: acc[kg][qi], K via transposed coalesced LDG ----
  float acc[4][8];
#pragma unroll
  for (int kg = 0; kg < 4; kg++)
#pragma unroll
    for (int qi = 0; qi < 8; qi++) acc[kg][qi] = 0.f;

#pragma unroll
  for (int c = 0; c < 8; c++) {
    const float* kp = &g_kT[(h * HD + c * 4) * NK + kbase];
    float4 kq0 = *(const float4*)&kp[0 * NK];
    float4 kq1 = *(const float4*)&kp[1 * NK];
    float4 kq2 = *(const float4*)&kp[2 * NK];
    float4 kq3 = *(const float4*)&kp[3 * NK];
#pragma unroll
    for (int qi = 0; qi < 8; qi++) {
      float4 qv = *(const float4*)&S.sQ[qi][c * 4];
      acc[0][qi] = fmaf(qv.x, kq0.x, acc[0][qi]);
      acc[0][qi] = fmaf(qv.y, kq1.x, acc[0][qi]);
      acc[0][qi] = fmaf(qv.z, kq2.x, acc[0][qi]);
      acc[0][qi] = fmaf(qv.w, kq3.x, acc[0][qi]);
      acc[1][qi] = fmaf(qv.x, kq0.y, acc[1][qi]);
      acc[1][qi] = fmaf(qv.y, kq1.y, acc[1][qi]);
      acc[1][qi] = fmaf(qv.z, kq2.y, acc[1][qi]);
      acc[1][qi] = fmaf(qv.w, kq3.y, acc[1][qi]);
      acc[2][qi] = fmaf(qv.x, kq0.z, acc[2][qi]);
      acc[2][qi] = fmaf(qv.y, kq1.z, acc[2][qi]);
      acc[2][qi] = fmaf(qv.z, kq2.z, acc[2][qi]);
      acc[2][qi] = fmaf(qv.w, kq3.z, acc[2][qi]);
      acc[3][qi] = fmaf(qv.x, kq0.w, acc[3][qi]);
      acc[3][qi] = fmaf(qv.y, kq1.w, acc[3][qi]);
      acc[3][qi] = fmaf(qv.z, kq2.w, acc[3][qi]);
      acc[3][qi] = fmaf(qv.w, kq3.w, acc[3][qi]);
    }
  }

  // ---- CPB bias + padding ----
  {
    float4 p4 = *(const float4*)&pad[kbase];
    float pv[4] = {100.f * p4.x, 100.f * p4.y, 100.f * p4.z, 100.f * p4.w};
#pragma unroll
    for (int qi = 0; qi < 8; qi++) {
      float4 a4 = *(const float4*)&am[(q0 + qi) * NK + kbase];
      ushort4 x4 = *(const ushort4*)&g_sidx[(q0 + qi) * NK + kbase];
      acc[0][qi] += fmaf(a4.x, S.sF[x4.x], S.sG[x4.x]) - pv[0];
      acc[1][qi] += fmaf(a4.y, S.sF[x4.y], S.sG[x4.y]) - pv[1];
      acc[2][qi] += fmaf(a4.z, S.sF[x4.z], S.sG[x4.z]) - pv[2];
      acc[3][qi] += fmaf(a4.w, S.sF[x4.w], S.sG[x4.w]) - pv[3];
    }
  }

  // ---- block max per query ----
  float m[8];
#pragma unroll
  for (int qi = 0; qi < 8; qi++)
    m[qi] = fmaxf(fmaxf(acc[0][qi], acc[1][qi]), fmaxf(acc[2][qi], acc[3][qi]));
#pragma unroll
  for (int o = 16; o; o >>= 1)
#pragma unroll
    for (int qi = 0; qi < 8; qi++)
      m[qi] = fmaxf(m[qi], __shfl_xor_sync(FULLMASK, m[qi], o));
  if (lane == 0)
#pragma unroll
    for (int qi = 0; qi < 8; qi++) S.sRed[qi][w] = m[qi];
  __syncthreads();
#pragma unroll
  for (int qi = 0; qi < 8; qi++) {
    float4 r0 = *(const float4*)&S.sRed[qi][0];
    float4 r1 = *(const float4*)&S.sRed[qi][4];
    m[qi] = fmaxf(fmaxf(fmaxf(r0.x, r0.y), fmaxf(r0.z, r0.w)),
                  fmaxf(fmaxf(r1.x, r1.y), fmaxf(r1.z, r1.w)));
  }

  // ---- exp + sum ----
  float s[8];
#pragma unroll
  for (int qi = 0; qi < 8; qi++) {
    float e0 = __expf(acc[0][qi] - m[qi]);
    float e1 = __expf(acc[1][qi] - m[qi]);
    float e2 = __expf(acc[2][qi] - m[qi]);
    float e3 = __expf(acc[3][qi] - m[qi]);
    acc[0][qi] = e0;
    acc[1][qi] = e1;
    acc[2][qi] = e2;
    acc[3][qi] = e3;
    s[qi] = (e0 + e1) + (e2 + e3);
  }
#pragma unroll
  for (int o = 16; o; o >>= 1)
#pragma unroll
    for (int qi = 0; qi < 8; qi++)
      s[qi] += __shfl_xor_sync(FULLMASK, s[qi], o);
  __syncthreads();  // all sRed max reads done
  if (lane == 0)
#pragma unroll
    for (int qi = 0; qi < 8; qi++) S.sRed[qi][w] = s[qi];
  __syncthreads();
  float inv[8];
#pragma unroll
  for (int qi = 0; qi < 8; qi++) {
    float4 r0 = *(const float4*)&S.sRed[qi][0];
    float4 r1 = *(const float4*)&S.sRed[qi][4];
    inv[qi] = 1.f / ((r0.x + r0.y) + (r0.z + r0.w) + (r1.x + r1.y) + (r1.z + r1.w));
  }

  // ---- AV in two qi-passes (sP holds 4 queries per pass) ----
  unsigned long long out2[4] = {0ull, 0ull, 0ull, 0ull};
  const float* vb = &g_v[(w * 128) * DIM + h * HD + lane];
#pragma unroll 1
  for (int pass = 0; pass < 2; pass++) {
    int qb = pass * 4;
#pragma unroll
    for (int kg = 0; kg < 4; kg++)
      *(float4*)&S.u.sP[kbase + kg][0] =
          make_float4(acc[kg][qb + 0] * inv[qb + 0], acc[kg][qb + 1] * inv[qb + 1],
                      acc[kg][qb + 2] * inv[qb + 2], acc[kg][qb + 3] * inv[qb + 3]);
    __syncthreads();
#pragma unroll 8
    for (int jj = 0; jj < 128; jj++) {
      float vv = __ldg(&vb[jj * DIM]);
      unsigned long long vvp = pk2(vv, vv);
      ulonglong2 p01 = *(const ulonglong2*)&S.u.sP[w * 128 + jj][0];
      fma2(out2[pass * 2 + 0], p01.x, vvp);
      fma2(out2[pass * 2 + 1], p01.y, vvp);
    }
    __syncthreads();  // pass reads done before next store / epilogue alias
  }

  // ---- cross-warp x reduction into sQ (x-slice [8q][32d]) ----
  float out[8];
#pragma unroll
  for (int p = 0; p < 4; p++) upk2(out[2 * p], out[2 * p + 1], out2[p]);
#pragma unroll
  for (int qi = 0; qi < 8; qi++) S.u.sOut[w][qi][lane] = out[qi];
  __syncthreads();
  {
    float accf = 0.f;
#pragma unroll
    for (int ww = 0; ww < 8; ww++) accf += S.u.sOut[ww][w][lane];
    S.sQ[w][lane] = accf;  // x[q0+w][h*32+lane]
  }
  __syncthreads();

  // ---- fused output projection: (8x32 x-slice) @ Wp[h*32: , :] ----
  // thread t owns output column t; atomicAdd partial into d_out.
  float acc8[8] = {};
  const float* wp = &Wp[(h * HD) * DIM + t];
#pragma unroll
  for (int d4 = 0; d4 < 8; d4++) {
    float wv0 = __ldg(&wp[(d4 * 4 + 0) * DIM]);
    float wv1 = __ldg(&wp[(d4 * 4 + 1) * DIM]);
    float wv2 = __ldg(&wp[(d4 * 4 + 2) * DIM]);
    float wv3 = __ldg(&wp[(d4 * 4 + 3) * DIM]);
#pragma unroll
    for (int qi = 0; qi < 8; qi++) {
      float4 xv = *(const float4*)&S.sQ[qi][d4 * 4];
      acc8[qi] = fmaf(xv.x, wv0, acc8[qi]);
      acc8[qi] = fmaf(xv.y, wv1, acc8[qi]);
      acc8[qi] = fmaf(xv.z, wv2, acc8[qi]);
      acc8[qi] = fmaf(xv.w, wv3, acc8[qi]);
    }
  }
#pragma unroll
  for (int qi = 0; qi < 8; qi++)
    atomicAdd(&outp[(q0 + qi) * DIM + t], acc8[qi]);
}

// ---------------- launch ------------------------------------------------
extern "C" void kernel_launch(void* const* d_in, const int* in_sizes, int n_in,
                              void* d_out, int out_size) {
  const float* query = (const float*)d_in[0];
  const float* kin   = (const float*)d_in[1];
  const float* vin   = (const float*)d_in[2];
  const float* pad   = (const float*)d_in[3];
  const float* am    = (const float*)d_in[4];
  const float* Wq    = (const float*)d_in[5];
  const float* bq    = (const float*)d_in[6];
  const float* Wk    = (const float*)d_in[7];
  const float* bk    = (const float*)d_in[8];
  const float* Wv    = (const float*)d_in[9];
  const float* bv    = (const float*)d_in[10];
  const float* Wp    = (const float*)d_in[11];
  const float* bp    = (const float*)d_in[12];
  const float* W1    = (const float*)d_in[13];
  const float* b1    = (const float*)d_in[14];
  const float* W2    = (const float*)d_in[15];
  float* out = (float*)d_out;

  prep<<<161, 512>>>(query, kin, vin, Wq, bq, Wk, bk, Wv, bv, W1, b1, W2);
  cpb_index<<<NQ * NK / 4 / 256, 256>>>(am, bp, out);
  attention<<<dim3(NQ / 8, HEADS), 256>>>(pad, am, Wp, out);
}

// round 10
// speedup vs baseline: 1.0551x; 1.0551x over previous
#include <cuda_runtime.h>
#include <math.h>

#define NQ 512
#define NK 1024
#define DIM 256
#define HEADS 8
#define HD 32
#define RPE 512
#define SCALE 0.17677669529663687f
#define FULLMASK 0xffffffffu

// ---------------- packed fp32x2 helpers ----------------------------------
__device__ __forceinline__ unsigned long long pk2(float lo, float hi) {
  unsigned long long r;
  asm("mov.b64 %0, {%1, %2};" : "=l"(r) : "f"(lo), "f"(hi));
  return r;
}
__device__ __forceinline__ void upk2(float& lo, float& hi, unsigned long long v) {
  asm("mov.b64 {%0, %1}, %2;" : "=f"(lo), "=f"(hi) : "l"(v));
}
__device__ __forceinline__ void fma2(unsigned long long& d, unsigned long long a,
                                     unsigned long long b) {
  asm("fma.rn.f32x2 %0, %1, %2, %0;" : "+l"(d) : "l"(a), "l"(b));
}

// ---------------- scratch (device globals; no allocation) ----------------
__device__ float g_q[NQ * DIM];
__device__ float g_kT[DIM * NK];  // K TRANSPOSED: [d][key]
__device__ float g_v[NK * DIM];
__device__ float g_tsort[RPE];
__device__ float g_F[HEADS * (RPE + 1)];
__device__ float g_G[HEADS * (RPE + 1)];
__device__ unsigned short g_sidx[NQ * NK];

// ---------------- QKV GEMM 32x64 tiles, 128 threads, 4x4/thread ----------
// blockIdx.z: 0 -> q proj, 1 -> k proj (TRANSPOSED store), 2 -> v proj
__global__ void __launch_bounds__(128) gemm_qkv(
    const float* __restrict__ query, const float* __restrict__ kin,
    const float* __restrict__ vin,
    const float* __restrict__ Wq, const float* __restrict__ bq,
    const float* __restrict__ Wk, const float* __restrict__ bk,
    const float* __restrict__ Wv, const float* __restrict__ bv) {
  __shared__ float As[16][36];
  __shared__ float Bs[16][64];

  int sel = blockIdx.z;
  const float* A = (sel == 0) ? query : (sel == 1) ? kin : vin;
  const float* W = (sel == 0) ? Wq : (sel == 1) ? Wk : Wv;
  const float* bias = (sel == 0) ? bq : (sel == 1) ? bk : bv;
  float* C = (sel == 0) ? g_q : (sel == 1) ? g_kT : g_v;
  int M = (sel == 0) ? NQ : NK;

  int bm = blockIdx.x * 32;
  if (bm >= M) return;
  int bn = blockIdx.y * 64;

  int t = threadIdx.x;
  int tx = t % 16, ty = t / 16;
  float acc[4][4] = {};

  for (int k0 = 0; k0 < 256; k0 += 16) {
    {
      int r = t >> 2, c4 = t & 3;
      float4 av = *(const float4*)&A[(bm + r) * 256 + k0 + c4 * 4];
      As[c4 * 4 + 0][r] = av.x;
      As[c4 * 4 + 1][r] = av.y;
      As[c4 * 4 + 2][r] = av.z;
      As[c4 * 4 + 3][r] = av.w;
    }
    {
#pragma unroll
      for (int u = 0; u < 2; u++) {
        int idx = t * 2 + u;
        int r = idx >> 4, c4 = idx & 15;
        *(float4*)&Bs[r][c4 * 4] = *(const float4*)&W[(k0 + r) * 256 + bn + c4 * 4];
      }
    }
    __syncthreads();
#pragma unroll
    for (int k = 0; k < 16; k++) {
      float a[4], b[4];
#pragma unroll
      for (int i = 0; i < 4; i++) a[i] = As[k][ty * 4 + i];
#pragma unroll
      for (int j = 0; j < 4; j++) b[j] = Bs[k][tx * 4 + j];
#pragma unroll
      for (int i = 0; i < 4; i++)
#pragma unroll
        for (int j = 0; j < 4; j++) acc[i][j] = fmaf(a[i], b[j], acc[i][j]);
    }
    __syncthreads();
  }
  if (sel == 1) {  // transposed: g_kT[col][row]
#pragma unroll
    for (int i = 0; i < 4; i++) {
      int row = bm + ty * 4 + i;
#pragma unroll
      for (int j = 0; j < 4; j++) {
        int col = bn + tx * 4 + j;
        C[col * NK + row] = acc[i][j] + bias[col];
      }
    }
  } else {
#pragma unroll
    for (int i = 0; i < 4; i++) {
      int row = bm + ty * 4 + i;
#pragma unroll
      for (int j = 0; j < 4; j++) {
        int col = bn + tx * 4 + j;
        C[row * 256 + col] = acc[i][j] + bias[col];
      }
    }
  }
}

// ---------------- CPB precompute: sort + shfl-based vector scans ---------
__global__ void __launch_bounds__(512) cpb_precompute(
    const float* __restrict__ W1v, const float* __restrict__ b1v,
    const float* __restrict__ W2v) {
  __shared__ float skey[RPE];
  __shared__ int sord[RPE];
  __shared__ float swtA[16][8];
  __shared__ float swtB[16][8];
  __shared__ float sF0[8], sG0[8];
  __shared__ float sTotW[8], sTotB[8];
  int t = threadIdx.x, lane = t & 31, warp = t >> 5;

  float w1 = W1v[t], bb = b1v[t];
  skey[t] = (w1 != 0.f) ? (-bb / w1) : INFINITY;
  sord[t] = t;
  __syncthreads();

  for (int size = 2; size <= RPE; size <<= 1) {
    for (int stride = size >> 1; stride > 0; stride >>= 1) {
      int p = t ^ stride;
      if (p > t) {
        bool asc = ((t & size) == 0);
        float k1 = skey[t], k2 = skey[p];
        if ((k1 > k2) == asc) {
          skey[t] = k2;
          skey[p] = k1;
          int tmp = sord[t];
          sord[t] = sord[p];
          sord[p] = tmp;
        }
      }
      __syncthreads();
    }
  }
  g_tsort[t] = skey[t];
  int r = sord[t];
  float w1r = W1v[r], b1r = b1v[r];
  bool isPos = (w1r > 0.f), isNeg = (w1r < 0.f);
  bool isZero = (!isPos && !isNeg);
  float sgn = isPos ? 1.f : (isNeg ? -1.f : 0.f);

  float ocw[8], ocb[8], cw[8], cb[8], f0[8], g0[8];
#pragma unroll
  for (int h = 0; h < 8; h++) {
    float w2 = W2v[r * HEADS + h];
    ocw[h] = sgn * w1r * w2;
    ocb[h] = sgn * b1r * w2;
    cw[h] = ocw[h];
    cb[h] = ocb[h];
    f0[h] = isNeg ? (w1r * w2) : 0.f;
    g0[h] = isNeg ? (b1r * w2) : ((isZero && b1r > 0.f) ? (b1r * w2) : 0.f);
  }

#pragma unroll
  for (int o = 16; o; o >>= 1)
#pragma unroll
    for (int h = 0; h < 8; h++) {
      f0[h] += __shfl_xor_sync(FULLMASK, f0[h], o);
      g0[h] += __shfl_xor_sync(FULLMASK, g0[h], o);
    }
  if (lane == 0)
#pragma unroll
    for (int h = 0; h < 8; h++) {
      swtA[warp][h] = f0[h];
      swtB[warp][h] = g0[h];
    }
  __syncthreads();
  if (t < 8) {
    float sa = 0.f, sb = 0.f;
    for (int ww = 0; ww < 16; ww++) {
      sa += swtA[ww][t];
      sb += swtB[ww][t];
    }
    sF0[t] = sa;
    sG0[t] = sb;
  }
  __syncthreads();

#pragma unroll
  for (int o = 1; o < 32; o <<= 1) {
#pragma unroll
    for (int h = 0; h < 8; h++) {
      float ta = __shfl_up_sync(FULLMASK, cw[h], o);
      float tb = __shfl_up_sync(FULLMASK, cb[h], o);
      if (lane >= o) {
        cw[h] += ta;
        cb[h] += tb;
      }
    }
  }
  if (lane == 31)
#pragma unroll
    for (int h = 0; h < 8; h++) {
      swtA[warp][h] = cw[h];
      swtB[warp][h] = cb[h];
    }
  __syncthreads();

  if (warp == 0) {
    float va[8], vb[8], owa[8], owb[8];
#pragma unroll
    for (int h = 0; h < 8; h++) {
      owa[h] = (lane < 16) ? swtA[lane][h] : 0.f;
      owb[h] = (lane < 16) ? swtB[lane][h] : 0.f;
      va[h] = owa[h];
      vb[h] = owb[h];
    }
#pragma unroll
    for (int o = 1; o < 16; o <<= 1)
#pragma unroll
      for (int h = 0; h < 8; h++) {
        float ta = __shfl_up_sync(FULLMASK, va[h], o);
        float tb = __shfl_up_sync(FULLMASK, vb[h], o);
        if (lane >= o) {
          va[h] += ta;
          vb[h] += tb;
        }
      }
    if (lane < 16) {
#pragma unroll
      for (int h = 0; h < 8; h++) {
        swtA[lane][h] = va[h] - owa[h];
        swtB[lane][h] = vb[h] - owb[h];
        if (lane == 15) {
          sTotW[h] = va[h];
          sTotB[h] = vb[h];
        }
      }
    }
  }
  __syncthreads();

#pragma unroll
  for (int h = 0; h < 8; h++) {
    float excl = (cw[h] - ocw[h]) + swtA[warp][h];
    float exclb = (cb[h] - ocb[h]) + swtB[warp][h];
    g_F[h * (RPE + 1) + t] = sF0[h] + excl;
    g_G[h * (RPE + 1) + t] = sG0[h] + exclb;
  }
  if (t == 0)
#pragma unroll
    for (int h = 0; h < 8; h++) {
      g_F[h * (RPE + 1) + RPE] = sF0[h] + sTotW[h];
      g_G[h * (RPE + 1) + RPE] = sG0[h] + sTotB[h];
    }
}

// ---------------- cpb_index + output init (out = bp broadcast) ----------
__global__ void __launch_bounds__(256) cpb_index(const float* __restrict__ am,
                                                 const float* __restrict__ bp,
                                                 float* __restrict__ outp) {
  __shared__ float st[RPE];
  int t = threadIdx.x;
  for (int i = t; i < RPE; i += 256) st[i] = g_tsort[i];
  // init d_out row blockIdx.x with bias (attention atomically accumulates)
  outp[blockIdx.x * 256 + t] = bp[t];
  __syncthreads();
  int base = (blockIdx.x * 256 + t) * 4;
  float4 a4 = *(const float4*)&am[base];
  float av[4] = {a4.x, a4.y, a4.z, a4.w};
  unsigned short res[4];
#pragma unroll
  for (int u = 0; u < 4; u++) {
    int pos = 0;
#pragma unroll
    for (int sgm = 256; sgm >= 1; sgm >>= 1)
      if (st[pos + sgm - 1] < av[u]) pos += sgm;
    res[u] = (unsigned short)pos;
  }
  *(ushort4*)&g_sidx[base] = make_ushort4(res[0], res[1], res[2], res[3]);
}

// ---------------- fused attention + output projection --------------------
struct AttnSmem {
  float sQ[8][32];  // @0: scaled Q, later reused as x-slice for projection
  union {
    float sP[NK][4];       // 16KB: normalized probs for a 4-qi pass
    float sOut[8][8][32];  // 8KB epilogue
  } u;                     // @1024
  float sRed[8][8];        // @17408 (16B aligned)
  float sF[RPE + 4];
  float sG[RPE + 4];
};  // ~21.4KB -> static shared, 4 blocks/SM

__global__ void __launch_bounds__(256, 4) attention(
    const float* __restrict__ pad, const float* __restrict__ am,
    const float* __restrict__ Wp, float* __restrict__ outp) {
  __shared__ AttnSmem S;
  const int h = blockIdx.y;
  const int q0 = blockIdx.x * 8;
  const int t = threadIdx.x;
  const int lane = t & 31, w = t >> 5;
  const int kbase = 4 * t;

  S.sQ[w][lane] = g_q[(q0 + w) * DIM + h * HD + lane] * SCALE;
  for (int i = t; i <= RPE; i += 256) {
    S.sF[i] = g_F[h * (RPE + 1) + i];
    S.sG[i] = g_G[h * (RPE + 1) + i];
  }
  __syncthreads();

  // ---- QK: acc[kg][qi], K via transposed coalesced LDG ----
  float acc[4][8];
#pragma unroll
  for (int kg = 0; kg < 4; kg++)
#pragma unroll
    for (int qi = 0; qi < 8; qi++) acc[kg][qi] = 0.f;

#pragma unroll
  for (int c = 0; c < 8; c++) {
    const float* kp = &g_kT[(h * HD + c * 4) * NK + kbase];
    float4 kq0 = *(const float4*)&kp[0 * NK];
    float4 kq1 = *(const float4*)&kp[1 * NK];
    float4 kq2 = *(const float4*)&kp[2 * NK];
    float4 kq3 = *(const float4*)&kp[3 * NK];
#pragma unroll
    for (int qi = 0; qi < 8; qi++) {
      float4 qv = *(const float4*)&S.sQ[qi][c * 4];
      acc[0][qi] = fmaf(qv.x, kq0.x, acc[0][qi]);
      acc[0][qi] = fmaf(qv.y, kq1.x, acc[0][qi]);
      acc[0][qi] = fmaf(qv.z, kq2.x, acc[0][qi]);
      acc[0][qi] = fmaf(qv.w, kq3.x, acc[0][qi]);
      acc[1][qi] = fmaf(qv.x, kq0.y, acc[1][qi]);
      acc[1][qi] = fmaf(qv.y, kq1.y, acc[1][qi]);
      acc[1][qi] = fmaf(qv.z, kq2.y, acc[1][qi]);
      acc[1][qi] = fmaf(qv.w, kq3.y, acc[1][qi]);
      acc[2][qi] = fmaf(qv.x, kq0.z, acc[2][qi]);
      acc[2][qi] = fmaf(qv.y, kq1.z, acc[2][qi]);
      acc[2][qi] = fmaf(qv.z, kq2.z, acc[2][qi]);
      acc[2][qi] = fmaf(qv.w, kq3.z, acc[2][qi]);
      acc[3][qi] = fmaf(qv.x, kq0.w, acc[3][qi]);
      acc[3][qi] = fmaf(qv.y, kq1.w, acc[3][qi]);
      acc[3][qi] = fmaf(qv.z, kq2.w, acc[3][qi]);
      acc[3][qi] = fmaf(qv.w, kq3.w, acc[3][qi]);
    }
  }

  // ---- CPB bias + padding ----
  {
    float4 p4 = *(const float4*)&pad[kbase];
    float pv[4] = {100.f * p4.x, 100.f * p4.y, 100.f * p4.z, 100.f * p4.w};
#pragma unroll
    for (int qi = 0; qi < 8; qi++) {
      float4 a4 = *(const float4*)&am[(q0 + qi) * NK + kbase];
      ushort4 x4 = *(const ushort4*)&g_sidx[(q0 + qi) * NK + kbase];
      acc[0][qi] += fmaf(a4.x, S.sF[x4.x], S.sG[x4.x]) - pv[0];
      acc[1][qi] += fmaf(a4.y, S.sF[x4.y], S.sG[x4.y]) - pv[1];
      acc[2][qi] += fmaf(a4.z, S.sF[x4.z], S.sG[x4.z]) - pv[2];
      acc[3][qi] += fmaf(a4.w, S.sF[x4.w], S.sG[x4.w]) - pv[3];
    }
  }

  // ---- block max per query ----
  float m[8];
#pragma unroll
  for (int qi = 0; qi < 8; qi++)
    m[qi] = fmaxf(fmaxf(acc[0][qi], acc[1][qi]), fmaxf(acc[2][qi], acc[3][qi]));
#pragma unroll
  for (int o = 16; o; o >>= 1)
#pragma unroll
    for (int qi = 0; qi < 8; qi++)
      m[qi] = fmaxf(m[qi], __shfl_xor_sync(FULLMASK, m[qi], o));
  if (lane == 0)
#pragma unroll
    for (int qi = 0; qi < 8; qi++) S.sRed[qi][w] = m[qi];
  __syncthreads();
#pragma unroll
  for (int qi = 0; qi < 8; qi++) {
    float4 r0 = *(const float4*)&S.sRed[qi][0];
    float4 r1 = *(const float4*)&S.sRed[qi][4];
    m[qi] = fmaxf(fmaxf(fmaxf(r0.x, r0.y), fmaxf(r0.z, r0.w)),
                  fmaxf(fmaxf(r1.x, r1.y), fmaxf(r1.z, r1.w)));
  }

  // ---- exp + sum ----
  float s[8];
#pragma unroll
  for (int qi = 0; qi < 8; qi++) {
    float e0 = __expf(acc[0][qi] - m[qi]);
    float e1 = __expf(acc[1][qi] - m[qi]);
    float e2 = __expf(acc[2][qi] - m[qi]);
    float e3 = __expf(acc[3][qi] - m[qi]);
    acc[0][qi] = e0;
    acc[1][qi] = e1;
    acc[2][qi] = e2;
    acc[3][qi] = e3;
    s[qi] = (e0 + e1) + (e2 + e3);
  }
#pragma unroll
  for (int o = 16; o; o >>= 1)
#pragma unroll
    for (int qi = 0; qi < 8; qi++)
      s[qi] += __shfl_xor_sync(FULLMASK, s[qi], o);
  __syncthreads();  // all sRed max reads done
  if (lane == 0)
#pragma unroll
    for (int qi = 0; qi < 8; qi++) S.sRed[qi][w] = s[qi];
  __syncthreads();
  float inv[8];
#pragma unroll
  for (int qi = 0; qi < 8; qi++) {
    float4 r0 = *(const float4*)&S.sRed[qi][0];
    float4 r1 = *(const float4*)&S.sRed[qi][4];
    inv[qi] = 1.f / ((r0.x + r0.y) + (r0.z + r0.w) + (r1.x + r1.y) + (r1.z + r1.w));
  }

  // ---- AV in two qi-passes (sP holds 4 queries per pass) ----
  unsigned long long out2[4] = {0ull, 0ull, 0ull, 0ull};
  const float* vb = &g_v[(w * 128) * DIM + h * HD + lane];
#pragma unroll 1
  for (int pass = 0; pass < 2; pass++) {
    int qb = pass * 4;
#pragma unroll
    for (int kg = 0; kg < 4; kg++)
      *(float4*)&S.u.sP[kbase + kg][0] =
          make_float4(acc[kg][qb + 0] * inv[qb + 0], acc[kg][qb + 1] * inv[qb + 1],
                      acc[kg][qb + 2] * inv[qb + 2], acc[kg][qb + 3] * inv[qb + 3]);
    __syncthreads();
#pragma unroll 8
    for (int jj = 0; jj < 128; jj++) {
      float vv = __ldg(&vb[jj * DIM]);
      unsigned long long vvp = pk2(vv, vv);
      ulonglong2 p01 = *(const ulonglong2*)&S.u.sP[w * 128 + jj][0];
      fma2(out2[pass * 2 + 0], p01.x, vvp);
      fma2(out2[pass * 2 + 1], p01.y, vvp);
    }
    __syncthreads();  // pass reads done before next store / epilogue alias
  }

  // ---- cross-warp x reduction into sQ (x-slice [8q][32d]) ----
  float out[8];
#pragma unroll
  for (int p = 0; p < 4; p++) upk2(out[2 * p], out[2 * p + 1], out2[p]);
#pragma unroll
  for (int qi = 0; qi < 8; qi++) S.u.sOut[w][qi][lane] = out[qi];
  __syncthreads();
  {
    float accf = 0.f;
#pragma unroll
    for (int ww = 0; ww < 8; ww++) accf += S.u.sOut[ww][w][lane];
    S.sQ[w][lane] = accf;  // x[q0+w][h*32+lane]
  }
  __syncthreads();

  // ---- fused output projection: (8x32 x-slice) @ Wp[h*32: , :] ----
  // thread t owns output column t; atomicAdd partial into d_out.
  float acc8[8] = {};
  const float* wp = &Wp[(h * HD) * DIM + t];
#pragma unroll
  for (int d4 = 0; d4 < 8; d4++) {
    float wv0 = __ldg(&wp[(d4 * 4 + 0) * DIM]);
    float wv1 = __ldg(&wp[(d4 * 4 + 1) * DIM]);
    float wv2 = __ldg(&wp[(d4 * 4 + 2) * DIM]);
    float wv3 = __ldg(&wp[(d4 * 4 + 3) * DIM]);
#pragma unroll
    for (int qi = 0; qi < 8; qi++) {
      float4 xv = *(const float4*)&S.sQ[qi][d4 * 4];
      acc8[qi] = fmaf(xv.x, wv0, acc8[qi]);
      acc8[qi] = fmaf(xv.y, wv1, acc8[qi]);
      acc8[qi] = fmaf(xv.z, wv2, acc8[qi]);
      acc8[qi] = fmaf(xv.w, wv3, acc8[qi]);
    }
  }
#pragma unroll
  for (int qi = 0; qi < 8; qi++)
    atomicAdd(&outp[(q0 + qi) * DIM + t], acc8[qi]);
}

// ---------------- launch ------------------------------------------------
extern "C" void kernel_launch(void* const* d_in, const int* in_sizes, int n_in,
                              void* d_out, int out_size) {
  const float* query = (const float*)d_in[0];
  const float* kin   = (const float*)d_in[1];
  const float* vin   = (const float*)d_in[2];
  const float* pad   = (const float*)d_in[3];
  const float* am    = (const float*)d_in[4];
  const float* Wq    = (const float*)d_in[5];
  const float* bq    = (const float*)d_in[6];
  const float* Wk    = (const float*)d_in[7];
  const float* bk    = (const float*)d_in[8];
  const float* Wv    = (const float*)d_in[9];
  const float* bv    = (const float*)d_in[10];
  const float* Wp    = (const float*)d_in[11];
  const float* bp    = (const float*)d_in[12];
  const float* W1    = (const float*)d_in[13];
  const float* b1    = (const float*)d_in[14];
  const float* W2    = (const float*)d_in[15];
  float* out = (float*)d_out;

  gemm_qkv<<<dim3(32, 4, 3), 128>>>(query, kin, vin, Wq, bq, Wk, bk, Wv, bv);
  cpb_precompute<<<1, RPE>>>(W1, b1, W2);
  cpb_index<<<NQ * NK / 4 / 256, 256>>>(am, bp, out);
  attention<<<dim3(NQ / 8, HEADS), 256>>>(pad, am, Wp, out);
}

// round 12
// speedup vs baseline: 1.2482x; 1.1830x over previous
#include <cuda_runtime.h>
#include <math.h>

#define NQ 512
#define NK 1024
#define DIM 256
#define HEADS 8
#define HD 32
#define RPE 512
#define SCALE 0.17677669529663687f
#define FULLMASK 0xffffffffu

// ---------------- packed fp32x2 helpers ----------------------------------
__device__ __forceinline__ unsigned long long pk2(float lo, float hi) {
  unsigned long long r;
  asm("mov.b64 %0, {%1, %2};" : "=l"(r) : "f"(lo), "f"(hi));
  return r;
}
__device__ __forceinline__ void upk2(float& lo, float& hi, unsigned long long v) {
  asm("mov.b64 {%0, %1}, %2;" : "=f"(lo), "=f"(hi) : "l"(v));
}
__device__ __forceinline__ void fma2(unsigned long long& d, unsigned long long a,
                                     unsigned long long b) {
  asm("fma.rn.f32x2 %0, %1, %2, %0;" : "+l"(d) : "l"(a), "l"(b));
}

// ---------------- scratch (device globals; no allocation) ----------------
__device__ float g_q[NQ * DIM];
__device__ float g_kT[DIM * NK];  // K TRANSPOSED: [d][key]
__device__ float g_v[NK * DIM];
__device__ float g_tsort[RPE];
__device__ float g_F[HEADS * (RPE + 1)];
__device__ float g_G[HEADS * (RPE + 1)];
__device__ unsigned short g_sidx[NQ * NK];

// ---------------- front: QKV GEMMs (4 tiles/block) + CPB precompute ------
// blocks 0..95: four independent 128-thread GEMM tile groups each
//   tile id = blockIdx.x*4+g: sel = id/128 (0=q,1=kT,2=v), tloc = id%128,
//   bm=(tloc>>2)*32, bn=(tloc&3)*64.
// block 96: CPB sort + prefix tables (512 threads).
__global__ void __launch_bounds__(512) front(
    const float* __restrict__ query, const float* __restrict__ kin,
    const float* __restrict__ vin,
    const float* __restrict__ Wq, const float* __restrict__ bq,
    const float* __restrict__ Wk, const float* __restrict__ bk,
    const float* __restrict__ Wv, const float* __restrict__ bv,
    const float* __restrict__ W1v, const float* __restrict__ b1v,
    const float* __restrict__ W2v) {
  int t = threadIdx.x;
  if (blockIdx.x < 96) {
    __shared__ float As[4][16][36];
    __shared__ float Bs[4][16][64];
    int g = t >> 7;       // tile group 0..3
    int lt = t & 127;     // thread within group
    int id = blockIdx.x * 4 + g;
    int sel = id >> 7;    // 0,1,2
    int tloc = id & 127;
    const float* A = (sel == 0) ? query : (sel == 1) ? kin : vin;
    const float* W = (sel == 0) ? Wq : (sel == 1) ? Wk : Wv;
    const float* bias = (sel == 0) ? bq : (sel == 1) ? bk : bv;
    float* C = (sel == 0) ? g_q : (sel == 1) ? g_kT : g_v;
    int M = (sel == 0) ? NQ : NK;
    int bm = (tloc >> 2) * 32;
    int bn = (tloc & 3) * 64;
    bool active = (bm < M);

    int tx = lt % 16, ty = lt / 16;
    float acc[4][4] = {};

    for (int k0 = 0; k0 < 256; k0 += 16) {
      if (active) {
        int r = lt >> 2, c4 = lt & 3;
        float4 av = *(const float4*)&A[(bm + r) * 256 + k0 + c4 * 4];
        As[g][c4 * 4 + 0][r] = av.x;
        As[g][c4 * 4 + 1][r] = av.y;
        As[g][c4 * 4 + 2][r] = av.z;
        As[g][c4 * 4 + 3][r] = av.w;
#pragma unroll
        for (int u = 0; u < 2; u++) {
          int idx = lt * 2 + u;
          int rr = idx >> 4, cc = idx & 15;
          *(float4*)&Bs[g][rr][cc * 4] =
              *(const float4*)&W[(k0 + rr) * 256 + bn + cc * 4];
        }
      }
      __syncthreads();
      if (active) {
#pragma unroll
        for (int k = 0; k < 16; k++) {
          float a[4], b[4];
#pragma unroll
          for (int i = 0; i < 4; i++) a[i] = As[g][k][ty * 4 + i];
#pragma unroll
          for (int j = 0; j < 4; j++) b[j] = Bs[g][k][tx * 4 + j];
#pragma unroll
          for (int i = 0; i < 4; i++)
#pragma unroll
            for (int j = 0; j < 4; j++) acc[i][j] = fmaf(a[i], b[j], acc[i][j]);
        }
      }
      __syncthreads();
    }
    if (active) {
      if (sel == 1) {  // transposed store: g_kT[col][row]
#pragma unroll
        for (int i = 0; i < 4; i++) {
          int row = bm + ty * 4 + i;
#pragma unroll
          for (int j = 0; j < 4; j++) {
            int col = bn + tx * 4 + j;
            C[col * NK + row] = acc[i][j] + bias[col];
          }
        }
      } else {
#pragma unroll
        for (int i = 0; i < 4; i++) {
          int row = bm + ty * 4 + i;
#pragma unroll
          for (int j = 0; j < 4; j++) {
            int col = bn + tx * 4 + j;
            C[row * 256 + col] = acc[i][j] + bias[col];
          }
        }
      }
    }
    return;
  }

  // ------------------ CPB precompute (block 96, 512 threads) ------------
  __shared__ float skey[RPE];
  __shared__ int sord[RPE];
  __shared__ float swtA[16][8];
  __shared__ float swtB[16][8];
  __shared__ float sF0[8], sG0[8];
  __shared__ float sTotW[8], sTotB[8];
  int lane = t & 31, warp = t >> 5;

  float w1 = W1v[t], bb = b1v[t];
  skey[t] = (w1 != 0.f) ? (-bb / w1) : INFINITY;
  sord[t] = t;
  __syncthreads();

  for (int size = 2; size <= RPE; size <<= 1) {
    for (int stride = size >> 1; stride > 0; stride >>= 1) {
      int p = t ^ stride;
      if (p > t) {
        bool asc = ((t & size) == 0);
        float k1 = skey[t], k2 = skey[p];
        if ((k1 > k2) == asc) {
          skey[t] = k2;
          skey[p] = k1;
          int tmp = sord[t];
          sord[t] = sord[p];
          sord[p] = tmp;
        }
      }
      __syncthreads();
    }
  }
  g_tsort[t] = skey[t];
  int r = sord[t];
  float w1r = W1v[r], b1r = b1v[r];
  bool isPos = (w1r > 0.f), isNeg = (w1r < 0.f);
  bool isZero = (!isPos && !isNeg);
  float sgn = isPos ? 1.f : (isNeg ? -1.f : 0.f);

  float ocw[8], ocb[8], cw[8], cb[8], f0[8], g0[8];
#pragma unroll
  for (int h = 0; h < 8; h++) {
    float w2 = W2v[r * HEADS + h];
    ocw[h] = sgn * w1r * w2;
    ocb[h] = sgn * b1r * w2;
    cw[h] = ocw[h];
    cb[h] = ocb[h];
    f0[h] = isNeg ? (w1r * w2) : 0.f;
    g0[h] = isNeg ? (b1r * w2) : ((isZero && b1r > 0.f) ? (b1r * w2) : 0.f);
  }

#pragma unroll
  for (int o = 16; o; o >>= 1)
#pragma unroll
    for (int h = 0; h < 8; h++) {
      f0[h] += __shfl_xor_sync(FULLMASK, f0[h], o);
      g0[h] += __shfl_xor_sync(FULLMASK, g0[h], o);
    }
  if (lane == 0)
#pragma unroll
    for (int h = 0; h < 8; h++) {
      swtA[warp][h] = f0[h];
      swtB[warp][h] = g0[h];
    }
  __syncthreads();
  if (t < 8) {
    float sa = 0.f, sb = 0.f;
    for (int ww = 0; ww < 16; ww++) {
      sa += swtA[ww][t];
      sb += swtB[ww][t];
    }
    sF0[t] = sa;
    sG0[t] = sb;
  }
  __syncthreads();

#pragma unroll
  for (int o = 1; o < 32; o <<= 1) {
#pragma unroll
    for (int h = 0; h < 8; h++) {
      float ta = __shfl_up_sync(FULLMASK, cw[h], o);
      float tb = __shfl_up_sync(FULLMASK, cb[h], o);
      if (lane >= o) {
        cw[h] += ta;
        cb[h] += tb;
      }
    }
  }
  if (lane == 31)
#pragma unroll
    for (int h = 0; h < 8; h++) {
      swtA[warp][h] = cw[h];
      swtB[warp][h] = cb[h];
    }
  __syncthreads();

  if (warp == 0) {
    float va[8], vb[8], owa[8], owb[8];
#pragma unroll
    for (int h = 0; h < 8; h++) {
      owa[h] = (lane < 16) ? swtA[lane][h] : 0.f;
      owb[h] = (lane < 16) ? swtB[lane][h] : 0.f;
      va[h] = owa[h];
      vb[h] = owb[h];
    }
#pragma unroll
    for (int o = 1; o < 16; o <<= 1)
#pragma unroll
      for (int h = 0; h < 8; h++) {
        float ta = __shfl_up_sync(FULLMASK, va[h], o);
        float tb = __shfl_up_sync(FULLMASK, vb[h], o);
        if (lane >= o) {
          va[h] += ta;
          vb[h] += tb;
        }
      }
    if (lane < 16) {
#pragma unroll
      for (int h = 0; h < 8; h++) {
        swtA[lane][h] = va[h] - owa[h];
        swtB[lane][h] = vb[h] - owb[h];
        if (lane == 15) {
          sTotW[h] = va[h];
          sTotB[h] = vb[h];
        }
      }
    }
  }
  __syncthreads();

#pragma unroll
  for (int h = 0; h < 8; h++) {
    float excl = (cw[h] - ocw[h]) + swtA[warp][h];
    float exclb = (cb[h] - ocb[h]) + swtB[warp][h];
    g_F[h * (RPE + 1) + t] = sF0[h] + excl;
    g_G[h * (RPE + 1) + t] = sG0[h] + exclb;
  }
  if (t == 0)
#pragma unroll
    for (int h = 0; h < 8; h++) {
      g_F[h * (RPE + 1) + RPE] = sF0[h] + sTotW[h];
      g_G[h * (RPE + 1) + RPE] = sG0[h] + sTotB[h];
    }
}

// ---------------- cpb_index + output init (out = bp broadcast) ----------
__global__ void __launch_bounds__(256) cpb_index(const float* __restrict__ am,
                                                 const float* __restrict__ bp,
                                                 float* __restrict__ outp) {
  __shared__ float st[RPE];
  int t = threadIdx.x;
  for (int i = t; i < RPE; i += 256) st[i] = g_tsort[i];
  // init d_out row blockIdx.x with bias (attention atomically accumulates)
  outp[blockIdx.x * 256 + t] = bp[t];
  __syncthreads();
  int base = (blockIdx.x * 256 + t) * 4;
  float4 a4 = *(const float4*)&am[base];
  float av[4] = {a4.x, a4.y, a4.z, a4.w};
  unsigned short res[4];
#pragma unroll
  for (int u = 0; u < 4; u++) {
    int pos = 0;
#pragma unroll
    for (int sgm = 256; sgm >= 1; sgm >>= 1)
      if (st[pos + sgm - 1] < av[u]) pos += sgm;
    res[u] = (unsigned short)pos;
  }
  *(ushort4*)&g_sidx[base] = make_ushort4(res[0], res[1], res[2], res[3]);
}

// ---------------- fused attention + output projection --------------------
struct AttnSmem {
  float sQ[8][32];  // @0: scaled Q, later reused as x-slice for projection
  union {
    float sP[NK][8];       // 32KB: normalized probs (single pass)
    float sOut[8][8][32];  // 8KB epilogue
  } u;                     // @1024
  float sRed[8][8];        // @33792 (16B aligned)
  float sF[RPE + 4];
  float sG[RPE + 4];
};  // ~37.3KB static

__global__ void __launch_bounds__(256, 4) attention(
    const float* __restrict__ pad, const float* __restrict__ am,
    const float* __restrict__ Wp, float* __restrict__ outp) {
  __shared__ AttnSmem S;
  const int h = blockIdx.y;
  const int q0 = blockIdx.x * 8;
  const int t = threadIdx.x;
  const int lane = t & 31, w = t >> 5;
  const int kbase = 4 * t;

  S.sQ[w][lane] = g_q[(q0 + w) * DIM + h * HD + lane] * SCALE;
  for (int i = t; i <= RPE; i += 256) {
    S.sF[i] = g_F[h * (RPE + 1) + i];
    S.sG[i] = g_G[h * (RPE + 1) + i];
  }
  __syncthreads();

  // ---- QK: acc[kg][qi], K via transposed coalesced LDG ----
  float acc[4][8];
#pragma unroll
  for (int kg = 0; kg < 4; kg++)
#pragma unroll
    for (int qi = 0; qi < 8; qi++) acc[kg][qi] = 0.f;

#pragma unroll
  for (int c = 0; c < 8; c++) {
    const float* kp = &g_kT[(h * HD + c * 4) * NK + kbase];
    float4 kq0 = *(const float4*)&kp[0 * NK];
    float4 kq1 = *(const float4*)&kp[1 * NK];
    float4 kq2 = *(const float4*)&kp[2 * NK];
    float4 kq3 = *(const float4*)&kp[3 * NK];
#pragma unroll
    for (int qi = 0; qi < 8; qi++) {
      float4 qv = *(const float4*)&S.sQ[qi][c * 4];
      acc[0][qi] = fmaf(qv.x, kq0.x, acc[0][qi]);
      acc[0][qi] = fmaf(qv.y, kq1.x, acc[0][qi]);
      acc[0][qi] = fmaf(qv.z, kq2.x, acc[0][qi]);
      acc[0][qi] = fmaf(qv.w, kq3.x, acc[0][qi]);
      acc[1][qi] = fmaf(qv.x, kq0.y, acc[1][qi]);
      acc[1][qi] = fmaf(qv.y, kq1.y, acc[1][qi]);
      acc[1][qi] = fmaf(qv.z, kq2.y, acc[1][qi]);
      acc[1][qi] = fmaf(qv.w, kq3.y, acc[1][qi]);
      acc[2][qi] = fmaf(qv.x, kq0.z, acc[2][qi]);
      acc[2][qi] = fmaf(qv.y, kq1.z, acc[2][qi]);
      acc[2][qi] = fmaf(qv.z, kq2.z, acc[2][qi]);
      acc[2][qi] = fmaf(qv.w, kq3.z, acc[2][qi]);
      acc[3][qi] = fmaf(qv.x, kq0.w, acc[3][qi]);
      acc[3][qi] = fmaf(qv.y, kq1.w, acc[3][qi]);
      acc[3][qi] = fmaf(qv.z, kq2.w, acc[3][qi]);
      acc[3][qi] = fmaf(qv.w, kq3.w, acc[3][qi]);
    }
  }

  // ---- CPB bias + padding ----
  {
    float4 p4 = *(const float4*)&pad[kbase];
    float pv[4] = {100.f * p4.x, 100.f * p4.y, 100.f * p4.z, 100.f * p4.w};
#pragma unroll
    for (int qi = 0; qi < 8; qi++) {
      float4 a4 = *(const float4*)&am[(q0 + qi) * NK + kbase];
      ushort4 x4 = *(const ushort4*)&g_sidx[(q0 + qi) * NK + kbase];
      acc[0][qi] += fmaf(a4.x, S.sF[x4.x], S.sG[x4.x]) - pv[0];
      acc[1][qi] += fmaf(a4.y, S.sF[x4.y], S.sG[x4.y]) - pv[1];
      acc[2][qi] += fmaf(a4.z, S.sF[x4.z], S.sG[x4.z]) - pv[2];
      acc[3][qi] += fmaf(a4.w, S.sF[x4.w], S.sG[x4.w]) - pv[3];
    }
  }

  // ---- block max per query ----
  float m[8];
#pragma unroll
  for (int qi = 0; qi < 8; qi++)
    m[qi] = fmaxf(fmaxf(acc[0][qi], acc[1][qi]), fmaxf(acc[2][qi], acc[3][qi]));
#pragma unroll
  for (int o = 16; o; o >>= 1)
#pragma unroll
    for (int qi = 0; qi < 8; qi++)
      m[qi] = fmaxf(m[qi], __shfl_xor_sync(FULLMASK, m[qi], o));
  if (lane == 0)
#pragma unroll
    for (int qi = 0; qi < 8; qi++) S.sRed[qi][w] = m[qi];
  __syncthreads();
#pragma unroll
  for (int qi = 0; qi < 8; qi++) {
    float4 r0 = *(const float4*)&S.sRed[qi][0];
    float4 r1 = *(const float4*)&S.sRed[qi][4];
    m[qi] = fmaxf(fmaxf(fmaxf(r0.x, r0.y), fmaxf(r0.z, r0.w)),
                  fmaxf(fmaxf(r1.x, r1.y), fmaxf(r1.z, r1.w)));
  }

  // ---- exp + sum ----
  float s[8];
#pragma unroll
  for (int qi = 0; qi < 8; qi++) {
    float e0 = __expf(acc[0][qi] - m[qi]);
    float e1 = __expf(acc[1][qi] - m[qi]);
    float e2 = __expf(acc[2][qi] - m[qi]);
    float e3 = __expf(acc[3][qi] - m[qi]);
    acc[0][qi] = e0;
    acc[1][qi] = e1;
    acc[2][qi] = e2;
    acc[3][qi] = e3;
    s[qi] = (e0 + e1) + (e2 + e3);
  }
#pragma unroll
  for (int o = 16; o; o >>= 1)
#pragma unroll
    for (int qi = 0; qi < 8; qi++)
      s[qi] += __shfl_xor_sync(FULLMASK, s[qi], o);
  __syncthreads();  // all sRed max reads done
  if (lane == 0)
#pragma unroll
    for (int qi = 0; qi < 8; qi++) S.sRed[qi][w] = s[qi];
  __syncthreads();
  float inv[8];
#pragma unroll
  for (int qi = 0; qi < 8; qi++) {
    float4 r0 = *(const float4*)&S.sRed[qi][0];
    float4 r1 = *(const float4*)&S.sRed[qi][4];
    inv[qi] = 1.f / ((r0.x + r0.y) + (r0.z + r0.w) + (r1.x + r1.y) + (r1.z + r1.w));
  }

  // ---- store NORMALIZED probs (all 8 queries, single pass) ----
#pragma unroll
  for (int kg = 0; kg < 4; kg++) {
    *(float4*)&S.u.sP[kbase + kg][0] =
        make_float4(acc[kg][0] * inv[0], acc[kg][1] * inv[1],
                    acc[kg][2] * inv[2], acc[kg][3] * inv[3]);
    *(float4*)&S.u.sP[kbase + kg][4] =
        make_float4(acc[kg][4] * inv[4], acc[kg][5] * inv[5],
                    acc[kg][6] * inv[6], acc[kg][7] * inv[7]);
  }
  __syncthreads();

  // ---- AV single pass: warp owns keys [w*128, w*128+128); f32x2 ----
  unsigned long long out2[4] = {0ull, 0ull, 0ull, 0ull};
  const float* vb = &g_v[(w * 128) * DIM + h * HD + lane];
#pragma unroll 8
  for (int jj = 0; jj < 128; jj++) {
    float vv = __ldg(&vb[jj * DIM]);
    unsigned long long vvp = pk2(vv, vv);
    ulonglong2 p01 = *(const ulonglong2*)&S.u.sP[w * 128 + jj][0];
    ulonglong2 p23 = *(const ulonglong2*)&S.u.sP[w * 128 + jj][4];
    fma2(out2[0], p01.x, vvp);
    fma2(out2[1], p01.y, vvp);
    fma2(out2[2], p23.x, vvp);
    fma2(out2[3], p23.y, vvp);
  }
  __syncthreads();  // all sP reads done before sOut alias write

  // ---- cross-warp x reduction into sQ (x-slice [8q][32d]) ----
  float out[8];
#pragma unroll
  for (int p = 0; p < 4; p++) upk2(out[2 * p], out[2 * p + 1], out2[p]);
#pragma unroll
  for (int qi = 0; qi < 8; qi++) S.u.sOut[w][qi][lane] = out[qi];
  __syncthreads();
  {
    float accf = 0.f;
#pragma unroll
    for (int ww = 0; ww < 8; ww++) accf += S.u.sOut[ww][w][lane];
    S.sQ[w][lane] = accf;  // x[q0+w][h*32+lane]
  }
  __syncthreads();

  // ---- fused output projection: (8x32 x-slice) @ Wp[h*32: , :] ----
  float acc8[8] = {};
  const float* wp = &Wp[(h * HD) * DIM + t];
#pragma unroll
  for (int d4 = 0; d4 < 8; d4++) {
    float wv0 = __ldg(&wp[(d4 * 4 + 0) * DIM]);
    float wv1 = __ldg(&wp[(d4 * 4 + 1) * DIM]);
    float wv2 = __ldg(&wp[(d4 * 4 + 2) * DIM]);
    float wv3 = __ldg(&wp[(d4 * 4 + 3) * DIM]);
#pragma unroll
    for (int qi = 0; qi < 8; qi++) {
      float4 xv = *(const float4*)&S.sQ[qi][d4 * 4];
      acc8[qi] = fmaf(xv.x, wv0, acc8[qi]);
      acc8[qi] = fmaf(xv.y, wv1, acc8[qi]);
      acc8[qi] = fmaf(xv.z, wv2, acc8[qi]);
      acc8[qi] = fmaf(xv.w, wv3, acc8[qi]);
    }
  }
#pragma unroll
  for (int qi = 0; qi < 8; qi++)
    atomicAdd(&outp[(q0 + qi) * DIM + t], acc8[qi]);
}

// ---------------- launch ------------------------------------------------
extern "C" void kernel_launch(void* const* d_in, const int* in_sizes, int n_in,
                              void* d_out, int out_size) {
  const float* query = (const float*)d_in[0];
  const float* kin   = (const float*)d_in[1];
  const float* vin   = (const float*)d_in[2];
  const float* pad   = (const float*)d_in[3];
  const float* am    = (const float*)d_in[4];
  const float* Wq    = (const float*)d_in[5];
  const float* bq    = (const float*)d_in[6];
  const float* Wk    = (const float*)d_in[7];
  const float* bk    = (const float*)d_in[8];
  const float* Wv    = (const float*)d_in[9];
  const float* bv    = (const float*)d_in[10];
  const float* Wp    = (const float*)d_in[11];
  const float* bp    = (const float*)d_in[12];
  const float* W1    = (const float*)d_in[13];
  const float* b1    = (const float*)d_in[14];
  const float* W2    = (const float*)d_in[15];
  float* out = (float*)d_out;

  front<<<97, 512>>>(query, kin, vin, Wq, bq, Wk, bk, Wv, bv, W1, b1, W2);
  cpb_index<<<NQ * NK / 4 / 256, 256>>>(am, bp, out);
  attention<<<dim3(NQ / 8, HEADS), 256>>>(pad, am, Wp, out);
}